// round 1
// baseline (speedup 1.0000x reference)
#include <cuda_runtime.h>

#define BATCH    8192
#define INS      64
#define OUTS     64
#define BV       32            // batch rows per thread
#define BTILE    32            // batch rows per block (TY=1)
#define NPAIR    (BV/2)        // 16 f32x2 pairs
#define XS_STRIDE 34           // pad: even (LDS.64 align) + conflict-free stores

// Packed f32x2 FMA (sm_100+/sm_103a FFMA2 — only reachable via PTX).
__device__ __forceinline__ float2 ffma2(float2 a, float2 b, float2 c) {
    float2 d;
    asm("{\n\t"
        ".reg .b64 ra, rb, rc, rd;\n\t"
        "mov.b64 ra, {%2, %3};\n\t"
        "mov.b64 rb, {%4, %5};\n\t"
        "mov.b64 rc, {%6, %7};\n\t"
        "fma.rn.f32x2 rd, ra, rb, rc;\n\t"
        "mov.b64 {%0, %1}, rd;\n\t"
        "}"
        : "=f"(d.x), "=f"(d.y)
        : "f"(a.x), "f"(a.y), "f"(b.x), "f"(b.y), "f"(c.x), "f"(c.y));
    return d;
}

__device__ __forceinline__ float2 relu2(float2 a) {
    a.x = fmaxf(a.x, 0.0f);
    a.y = fmaxf(a.y, 0.0f);
    return a;
}

__device__ __forceinline__ float2 bcast2(float v) { return make_float2(v, v); }

__global__ void __launch_bounds__(64, 8)
kan_kernel(const float* __restrict__ x,
           const float* __restrict__ w1, const float* __restrict__ b1,
           const float* __restrict__ w2, const float* __restrict__ b2,
           const float* __restrict__ w3, const float* __restrict__ b3,
           float* __restrict__ out)
{
    __shared__ float xs[INS * XS_STRIDE];

    const int o   = threadIdx.x;        // 0..63, one output column per thread
    const int b0  = blockIdx.x * BTILE; // batch tile base

    // Stage x tile transposed: xs[i][b_local]. Global reads coalesced over i.
    #pragma unroll
    for (int idx = o; idx < BTILE * INS; idx += 64) {
        int b = idx >> 6;       // /INS
        int i = idx & (INS - 1);
        xs[i * XS_STRIDE + b] = x[(b0 + b) * INS + i];
    }
    __syncthreads();

    float2 acc[NPAIR];
    #pragma unroll
    for (int j = 0; j < NPAIR; j++) acc[j] = make_float2(0.0f, 0.0f);
    float sb3 = 0.0f;   // sum_i b3[i,o] — batch-invariant, added once at the end

    const float2* __restrict__ w1v = (const float2*)w1;
    const float2* __restrict__ b1v = (const float2*)b1;
    const float4* __restrict__ w2v = (const float4*)w2;
    const float2* __restrict__ b2v = (const float2*)b2;
    const float2* __restrict__ w3v = (const float2*)w3;

    #pragma unroll 2
    for (int i = 0; i < INS; i++) {
        const int po = i * OUTS + o;
        const float2 W1 = __ldg(w1v + po);
        const float2 B1 = __ldg(b1v + po);
        const float4 W2 = __ldg(w2v + po);   // (k0h0, k0h1, k1h0, k1h1)
        const float2 B2 = __ldg(b2v + po);
        const float2 W3 = __ldg(w3v + po);
        const float  B3 = __ldg(b3 + po);
        sb3 += B3;

        // Broadcast params into packed pairs once per i (amortized over 16 pairs)
        const float2 w1a = bcast2(W1.x), w1b = bcast2(W1.y);
        const float2 b1a = bcast2(B1.x), b1b = bcast2(B1.y);
        const float2 wA  = bcast2(W2.x), wB = bcast2(W2.y);
        const float2 wC  = bcast2(W2.z), wD = bcast2(W2.w);
        const float2 b2a = bcast2(B2.x), b2b = bcast2(B2.y);
        const float2 w3a = bcast2(W3.x), w3b = bcast2(W3.y);

        const float* xrow = &xs[i * XS_STRIDE];

        #pragma unroll
        for (int j = 0; j < NPAIR; j++) {
            // LDS.64, warp-uniform address -> broadcast, conflict-free
            float2 xv = *(const float2*)(xrow + 2 * j);
            // layer 1: h1 = relu(x*w1 + b1), H1=2
            float2 t0 = relu2(ffma2(xv, w1a, b1a));
            float2 t1 = relu2(ffma2(xv, w1b, b1b));
            // layer 2: h2 = relu(W2 h1 + b2), H2=2
            float2 u0 = relu2(ffma2(t0, wA, ffma2(t1, wB, b2a)));
            float2 u1 = relu2(ffma2(t0, wC, ffma2(t1, wD, b2b)));
            // layer 3 + accumulate over i: acc += w3 . h2
            acc[j] = ffma2(u0, w3a, ffma2(u1, w3b, acc[j]));
        }
    }

    // Write out[b, o]; lanes (o) contiguous -> coalesced 256B per row
    #pragma unroll
    for (int j = 0; j < NPAIR; j++) {
        out[(b0 + 2 * j)     * OUTS + o] = acc[j].x + sb3;
        out[(b0 + 2 * j + 1) * OUTS + o] = acc[j].y + sb3;
    }
}

extern "C" void kernel_launch(void* const* d_in, const int* in_sizes, int n_in,
                              void* d_out, int out_size)
{
    const float* x  = (const float*)d_in[0];
    const float* w1 = (const float*)d_in[1];
    const float* b1 = (const float*)d_in[2];
    const float* w2 = (const float*)d_in[3];
    const float* b2 = (const float*)d_in[4];
    const float* w3 = (const float*)d_in[5];
    const float* b3 = (const float*)d_in[6];
    float* out = (float*)d_out;

    dim3 grid(BATCH / BTILE);   // 256 blocks
    dim3 block(64);
    kan_kernel<<<grid, block>>>(x, w1, b1, w2, b2, w3, b3, out);
}

// round 2
// speedup vs baseline: 1.2912x; 1.2912x over previous
#include <cuda_runtime.h>

#define BATCH    8192
#define INS      64
#define OUTS     64
#define BV       8             // batch rows per thread
#define BTILE    8             // batch rows per block
#define NPAIR    (BV/2)        // 4 f32x2 pairs
#define XS_STRIDE 8            // row stride (16B-aligned rows; broadcast reads)

// Packed f32x2 FMA (sm_100+/sm_103a FFMA2 — only reachable via PTX).
__device__ __forceinline__ float2 ffma2(float2 a, float2 b, float2 c) {
    float2 d;
    asm("{\n\t"
        ".reg .b64 ra, rb, rc, rd;\n\t"
        "mov.b64 ra, {%2, %3};\n\t"
        "mov.b64 rb, {%4, %5};\n\t"
        "mov.b64 rc, {%6, %7};\n\t"
        "fma.rn.f32x2 rd, ra, rb, rc;\n\t"
        "mov.b64 {%0, %1}, rd;\n\t"
        "}"
        : "=f"(d.x), "=f"(d.y)
        : "f"(a.x), "f"(a.y), "f"(b.x), "f"(b.y), "f"(c.x), "f"(c.y));
    return d;
}

__device__ __forceinline__ float2 relu2(float2 a) {
    a.x = fmaxf(a.x, 0.0f);
    a.y = fmaxf(a.y, 0.0f);
    return a;
}

__device__ __forceinline__ float2 bcast2(float v) { return make_float2(v, v); }

__global__ void __launch_bounds__(64)
kan_kernel(const float* __restrict__ x,
           const float* __restrict__ w1, const float* __restrict__ b1,
           const float* __restrict__ w2, const float* __restrict__ b2,
           const float* __restrict__ w3, const float* __restrict__ b3,
           float* __restrict__ out)
{
    __shared__ float xs[INS * XS_STRIDE];

    const int o   = threadIdx.x;        // 0..63, one output column per thread
    const int b0  = blockIdx.x * BTILE; // batch tile base

    // Stage x tile transposed: xs[i][b_local]. Global reads coalesced over i.
    #pragma unroll
    for (int idx = o; idx < BTILE * INS; idx += 64) {
        int b = idx >> 6;       // /INS
        int i = idx & (INS - 1);
        xs[i * XS_STRIDE + b] = x[(b0 + b) * INS + i];
    }
    __syncthreads();

    float2 acc[NPAIR];
    #pragma unroll
    for (int j = 0; j < NPAIR; j++) acc[j] = make_float2(0.0f, 0.0f);
    float sb3 = 0.0f;   // sum_i b3[i,o] — batch-invariant, added once at the end

    const float2* __restrict__ w1v = (const float2*)w1;
    const float2* __restrict__ b1v = (const float2*)b1;
    const float4* __restrict__ w2v = (const float4*)w2;
    const float2* __restrict__ b2v = (const float2*)b2;
    const float2* __restrict__ w3v = (const float2*)w3;

    #pragma unroll 4
    for (int i = 0; i < INS; i++) {
        const int po = i * OUTS + o;
        const float2 W1 = __ldg(w1v + po);
        const float2 B1 = __ldg(b1v + po);
        const float4 W2 = __ldg(w2v + po);   // (k0h0, k0h1, k1h0, k1h1)
        const float2 B2 = __ldg(b2v + po);
        const float2 W3 = __ldg(w3v + po);
        const float  B3 = __ldg(b3 + po);
        sb3 += B3;

        // Broadcast params into packed pairs once per i (amortized over pairs)
        const float2 w1a = bcast2(W1.x), w1b = bcast2(W1.y);
        const float2 b1a = bcast2(B1.x), b1b = bcast2(B1.y);
        const float2 wA  = bcast2(W2.x), wB = bcast2(W2.y);
        const float2 wC  = bcast2(W2.z), wD = bcast2(W2.w);
        const float2 b2a = bcast2(B2.x), b2b = bcast2(B2.y);
        const float2 w3a = bcast2(W3.x), w3b = bcast2(W3.y);

        const float* xrow = &xs[i * XS_STRIDE];

        // Hoist all x pairs (warp-uniform LDS -> broadcast, conflict-free)
        float2 xv[NPAIR];
        #pragma unroll
        for (int j = 0; j < NPAIR; j++)
            xv[j] = *(const float2*)(xrow + 2 * j);

        #pragma unroll
        for (int j = 0; j < NPAIR; j++) {
            // layer 1: h1 = relu(x*w1 + b1), H1=2
            float2 t0 = relu2(ffma2(xv[j], w1a, b1a));
            float2 t1 = relu2(ffma2(xv[j], w1b, b1b));
            // layer 2: h2 = relu(W2 h1 + b2), H2=2
            float2 u0 = relu2(ffma2(t0, wA, ffma2(t1, wB, b2a)));
            float2 u1 = relu2(ffma2(t0, wC, ffma2(t1, wD, b2b)));
            // layer 3 + accumulate over i: acc += w3 . h2
            acc[j] = ffma2(u0, w3a, ffma2(u1, w3b, acc[j]));
        }
    }

    // Write out[b, o]; lanes (o) contiguous -> coalesced 256B per row
    #pragma unroll
    for (int j = 0; j < NPAIR; j++) {
        out[(b0 + 2 * j)     * OUTS + o] = acc[j].x + sb3;
        out[(b0 + 2 * j + 1) * OUTS + o] = acc[j].y + sb3;
    }
}

extern "C" void kernel_launch(void* const* d_in, const int* in_sizes, int n_in,
                              void* d_out, int out_size)
{
    const float* x  = (const float*)d_in[0];
    const float* w1 = (const float*)d_in[1];
    const float* b1 = (const float*)d_in[2];
    const float* w2 = (const float*)d_in[3];
    const float* b2 = (const float*)d_in[4];
    const float* w3 = (const float*)d_in[5];
    const float* b3 = (const float*)d_in[6];
    float* out = (float*)d_out;

    dim3 grid(BATCH / BTILE);   // 1024 blocks
    dim3 block(64);
    kan_kernel<<<grid, block>>>(x, w1, b1, w2, b2, w3, b3, out);
}